// round 1
// baseline (speedup 1.0000x reference)
#include <cuda_runtime.h>
#include <cuda_bf16.h>

// Bilateral filter: B=8, C=3, H=W=512, K=5, sigma_s=2.0, sigma_r=0.1
// w(i,j) = spatial(i,j) * exp(-(n-c)^2 * 50)
//        = exp2( log2(spatial) - ((n-c)*C1)^2 ),  C1 = sqrt(50*log2(e))
// out = sum(w*n) / sum(w)   (wsum >= 1 from center tap, no clip needed)

#define HW 512
#define TILE 32
#define PAD 2
#define SMW (TILE + 2*PAD)   // 36
#define SMH (TILE + 2*PAD)   // 36

__device__ __forceinline__ float ex2_approx(float x) {
    float y;
    asm("ex2.approx.ftz.f32 %0, %1;" : "=f"(y) : "f"(x));
    return y;
}

__device__ __forceinline__ int reflect512(int g) {
    // valid for g in [-2, 513]
    g = (g < 0) ? -g : g;
    g = (g > 511) ? (1022 - g) : g;
    return g;
}

__global__ __launch_bounds__(256, 4)
void bilateral_kernel(const float* __restrict__ x,
                      const float* __restrict__ spatial,
                      float* __restrict__ out) {
    __shared__ float tile[SMH][SMW];
    __shared__ float ls[25];

    const int bx = blockIdx.x * TILE;
    const int by = blockIdx.y * TILE;
    const float* __restrict__ src = x   + (size_t)blockIdx.z * (HW * HW);
    float* __restrict__       dst = out + (size_t)blockIdx.z * (HW * HW);

    const int tid = threadIdx.y * 32 + threadIdx.x;

    if (tid < 25) {
        ls[tid] = __log2f(spatial[tid]);
    }

    // Cooperative tile load with reflect padding (36x36 = 1296 elems, 256 threads)
    #pragma unroll
    for (int idx = tid; idx < SMH * SMW; idx += 256) {
        int ly = idx / SMW;
        int lx = idx - ly * SMW;
        int gy = reflect512(by + ly - PAD);
        int gx = reflect512(bx + lx - PAD);
        tile[ly][lx] = src[gy * HW + gx];
    }
    __syncthreads();

    const float C1 = 8.4932165750422091f;  // sqrt(50 * log2(e))

    const int lx  = threadIdx.x;        // 0..31
    const int ly0 = threadIdx.y * 4;    // 0,4,...,28  (4 output rows per thread)

    float cC1[4], wsum[4], acc[4];
    #pragma unroll
    for (int k = 0; k < 4; k++) {
        float c = tile[ly0 + PAD + k][lx + PAD];
        cC1[k]  = c * C1;
        wsum[k] = 0.0f;
        acc[k]  = 0.0f;
    }

    #pragma unroll
    for (int j = 0; j < 5; j++) {
        // one 8-tall register column serves all 4 pixels' 5-tall windows
        float v[8];
        #pragma unroll
        for (int r = 0; r < 8; r++) {
            v[r] = tile[ly0 + r][lx + j];
        }
        #pragma unroll
        for (int i = 0; i < 5; i++) {
            const float lsij = ls[i * 5 + j];
            #pragma unroll
            for (int k = 0; k < 4; k++) {
                float n = v[i + k];
                float d = fmaf(n, C1, -cC1[k]);          // FFMA-imm (rt=1)
                float w = ex2_approx(fmaf(d, -d, lsij)); // FFMA + MUFU.EX2
                wsum[k] += w;
                acc[k]   = fmaf(w, n, acc[k]);
            }
        }
    }

    #pragma unroll
    for (int k = 0; k < 4; k++) {
        int gy = by + ly0 + k;
        int gx = bx + lx;
        dst[gy * HW + gx] = __fdividef(acc[k], wsum[k]);
    }
}

extern "C" void kernel_launch(void* const* d_in, const int* in_sizes, int n_in,
                              void* d_out, int out_size) {
    const float* x       = (const float*)d_in[0];  // (8,3,512,512)
    const float* spatial = (const float*)d_in[1];  // (5,5)
    float* out           = (float*)d_out;

    dim3 block(32, 8);
    dim3 grid(HW / TILE, HW / TILE, 24);  // 16 x 16 x (B*C)
    bilateral_kernel<<<grid, block>>>(x, spatial, out);
}